// round 12
// baseline (speedup 1.0000x reference)
#include <cuda_runtime.h>
#include <math.h>

#define BATCH 4
#define NPTS  8192
#define RT 128                      // rows per block
#define CSPLIT 4
#define CPB (NPTS / CSPLIT)         // 2048 cols per block
#define CHUNK 256                   // cols staged per chunk
#define NCH (CPB / CHUNK)           // 8 chunks
#define THREADS 256
#define NBLOCKS ((NPTS / RT) * CSPLIT * BATCH)   // 1024
#define MST 257                     // padded smem row stride (floats)

__device__ unsigned g_rmax[BATCH * NPTS];   // pred  -> label
__device__ unsigned g_cmax[BATCH * NPTS];   // label -> pred
__device__ unsigned g_counter = 0;

__device__ __forceinline__ unsigned enc(float f) {
    unsigned u = __float_as_uint(f);
    return u ^ ((unsigned)((int)u >> 31) | 0x80000000u);
}
__device__ __forceinline__ float dec(unsigned k) {
    unsigned u = (k & 0x80000000u) ? (k ^ 0x80000000u) : ~k;
    return __uint_as_float(u);
}
__device__ __forceinline__ float harvest(unsigned k) {
    return sqrtf(fmaxf(-2.0f * dec(k), 0.0f));
}

// One block: 128 pred rows x 2048 label cols (8 prefetched 256-col chunks).
// Per entry computes u = x.y - x^2/2 - y^2/2 = -d^2/2 once; BOTH direction
// maxes (row over cols, col over rows) take max of the same u.
// The LAST block to finish also performs the global finalize + reset.
__global__ __launch_bounds__(THREADS, 3)
void chamfer_main(const float* __restrict__ pred,
                  const float* __restrict__ label,
                  float* __restrict__ out) {
    const int b      = blockIdx.z;
    const int rbase  = blockIdx.x * RT;
    const int cb     = blockIdx.y * CPB;
    const float* __restrict__ A  = pred  + (size_t)b * NPTS * 3;
    const float* __restrict__ Bp = label + (size_t)b * NPTS * 3;

    __shared__ float4 sB[CHUNK];        // (bx, by, bz, nwy) per col, 4 KB
    __shared__ float  sM[16 * MST];     // merge transpose buffer, ~16 KB

    const int tid = threadIdx.x;
    const int rg  = tid >> 4;
    const int cg  = tid & 15;

    // ---- Prologue: this thread's 8 A rows (96 contiguous bytes) ----
    float ax[8], ay[8], az[8], nwx[8], rowm[8];
    {
        const int r0 = rbase + rg * 8;                  // 16B-aligned start
        const float4* Ar = (const float4*)(A + (size_t)r0 * 3);
        float av[24];
        #pragma unroll
        for (int i = 0; i < 6; i++) *(float4*)&av[4 * i] = Ar[i];
        #pragma unroll
        for (int r = 0; r < 8; r++) {
            ax[r] = av[3 * r + 0];
            ay[r] = av[3 * r + 1];
            az[r] = av[3 * r + 2];
            nwx[r] = -0.5f * fmaf(ax[r], ax[r], fmaf(ay[r], ay[r], az[r] * az[r]));
            rowm[r] = -3.0e38f;
        }
    }

    // Preload chunk 0's column for this thread.
    float nbx, nby, nbz;
    {
        const float* p = Bp + (size_t)(cb + tid) * 3;
        nbx = p[0]; nby = p[1]; nbz = p[2];
    }

    for (int ch = 0; ch < NCH; ch++) {
        __syncthreads();                                // sB free, prev sM reads done
        {
            const float bx = nbx, by = nby, bz = nbz;
            const float nwy = -0.5f * fmaf(bx, bx, fmaf(by, by, bz * bz));
            sB[tid] = make_float4(bx, by, bz, nwy);
        }
        __syncthreads();

        // Prefetch next chunk's column (hidden under compute).
        if (ch + 1 < NCH) {
            const float* p = Bp + (size_t)(cb + (ch + 1) * CHUNK + tid) * 3;
            nbx = p[0]; nby = p[1]; nbz = p[2];
        }

        float colm[16];
        #pragma unroll
        for (int k = 0; k < 16; k++) colm[k] = -3.0e38f;

        // Main compute: 16 cols x 8 rows, scalar FFMA (rt=2), maxes in regs.
        #pragma unroll
        for (int cc = 0; cc < 16; cc++) {
            const float4 v = sB[cc * 16 + cg];          // lanes -> consecutive float4s
            float cm = colm[cc];
            #pragma unroll
            for (int r = 0; r < 8; r++) {
                float t = fmaf(az[r], v.z, v.w);        // az*bz - y^2/2
                t = fmaf(ay[r], v.y, t);                // + ay*by
                t = fmaf(ax[r], v.x, t);                // + ax*bx
                t += nwx[r];                            // - x^2/2  => -d^2/2
                rowm[r] = fmaxf(rowm[r], t);
                cm = fmaxf(cm, t);
            }
            colm[cc] = cm;
        }

        // Col merge for this chunk: 16 rg writers per col through sM.
        #pragma unroll
        for (int cc = 0; cc < 16; cc++)
            sM[rg * MST + cc * 16 + cg] = colm[cc];
        __syncthreads();
        {
            float m = sM[tid];                          // col = tid of this chunk
            #pragma unroll
            for (int g = 1; g < 16; g++) m = fmaxf(m, sM[g * MST + tid]);
            atomicMax(&g_cmax[(size_t)b * NPTS + cb + ch * CHUNK + tid], enc(m));
        }
    }

    // ---- Row merge: transpose through smem, one RED per row ----
    __syncthreads();
    #pragma unroll
    for (int r = 0; r < 8; r++)
        sM[cg * MST + rg * 8 + r] = rowm[r];
    __syncthreads();
    if (tid < RT) {
        float m = sM[tid];
        #pragma unroll
        for (int g = 1; g < 16; g++) m = fmaxf(m, sM[g * MST + tid]);
        atomicMax(&g_rmax[(size_t)b * NPTS + rbase + tid], enc(m));
    }

    // ---- Last-block-done finalize ----
    __shared__ bool is_last;
    __threadfence();
    __syncthreads();
    if (tid == 0) {
        const unsigned done = atomicAdd(&g_counter, 1u) + 1u;
        is_last = (done == (unsigned)NBLOCKS);
    }
    __syncthreads();
    if (!is_last) return;

    // One block reads both max arrays (512 KB, L2-resident), harvests
    // sqrt(-2u), sums, writes the scalar, and resets scratch for replay.
    float s = 0.0f;
    uint4* r4 = (uint4*)g_rmax;   // 8192 uint4
    uint4* c4 = (uint4*)g_cmax;   // 8192 uint4
    const uint4 z4 = make_uint4(0u, 0u, 0u, 0u);
    #pragma unroll 4
    for (int k = 0; k < 8192 / THREADS; k++) {
        const int i = k * THREADS + tid;
        const uint4 a = r4[i];
        const uint4 c = c4[i];
        r4[i] = z4;
        c4[i] = z4;
        s += harvest(a.x) + harvest(a.y) + harvest(a.z) + harvest(a.w);
        s += harvest(c.x) + harvest(c.y) + harvest(c.z) + harvest(c.w);
    }

    #pragma unroll
    for (int off = 16; off > 0; off >>= 1)
        s += __shfl_down_sync(0xFFFFFFFFu, s, off);

    __shared__ float warp_sums[THREADS / 32];
    if ((tid & 31) == 0) warp_sums[tid >> 5] = s;
    __syncthreads();
    if (tid == 0) {
        float tot = 0.0f;
        #pragma unroll
        for (int w = 0; w < THREADS / 32; w++) tot += warp_sums[w];
        out[0] = tot * (1.0f / (float)(BATCH * NPTS));
        g_counter = 0u;                  // reset for next graph replay
    }
}

extern "C" void kernel_launch(void* const* d_in, const int* in_sizes, int n_in,
                              void* d_out, int out_size) {
    const float* pred  = (const float*)d_in[0];
    const float* label = (const float*)d_in[1];
    float* out = (float*)d_out;

    dim3 grid(NPTS / RT, CSPLIT, BATCH);   // 64 x 4 x 4 = 1024 blocks
    chamfer_main<<<grid, THREADS>>>(pred, label, out);
}

// round 13
// speedup vs baseline: 1.1737x; 1.1737x over previous
#include <cuda_runtime.h>
#include <math.h>

#define BATCH 4
#define NPTS  8192
#define RT 128                      // rows per block
#define CSPLIT 4
#define CPB (NPTS / CSPLIT)         // 2048 cols per block
#define CHUNK 256                   // cols staged per chunk
#define NCH (CPB / CHUNK)           // 8 chunks
#define THREADS 256
// rg = tid>>4 (16 row groups x 8 rows), cg = tid&15 (16 col slots x 16 cols/chunk)
#define FIN_THREADS 256
#define FIN_BLOCKS 64
#define MST 257                     // padded smem row stride (floats)

__device__ unsigned g_rmax[BATCH * NPTS];   // pred  -> label
__device__ unsigned g_cmax[BATCH * NPTS];   // label -> pred
__device__ float    g_bsum[FIN_BLOCKS];
__device__ unsigned g_counter = 0;

__device__ __forceinline__ unsigned enc(float f) {
    unsigned u = __float_as_uint(f);
    return u ^ ((unsigned)((int)u >> 31) | 0x80000000u);
}
__device__ __forceinline__ float dec(unsigned k) {
    unsigned u = (k & 0x80000000u) ? (k ^ 0x80000000u) : ~k;
    return __uint_as_float(u);
}

// One block: 128 pred rows x 2048 label cols (8 prefetched 256-col chunks).
// Per entry the FMA chain gives t = x.y - y^2/2; the row side maxes t
// directly (row-constant -x^2/2 folded once after the loop); the col side
// adds nwx to form u = -d^2/2.
__global__ __launch_bounds__(THREADS, 3)
void chamfer_main(const float* __restrict__ pred,
                  const float* __restrict__ label) {
    const int b      = blockIdx.z;
    const int rbase  = blockIdx.x * RT;
    const int cb     = blockIdx.y * CPB;
    const float* __restrict__ A  = pred  + (size_t)b * NPTS * 3;
    const float* __restrict__ Bp = label + (size_t)b * NPTS * 3;

    __shared__ float4 sB[CHUNK];        // (bx, by, bz, nwy) per col, 4 KB
    __shared__ float  sM[16 * MST];     // merge transpose buffer, ~16 KB

    const int tid = threadIdx.x;
    const int rg  = tid >> 4;
    const int cg  = tid & 15;

    // ---- Prologue: this thread's 8 A rows (96 contiguous bytes) ----
    float ax[8], ay[8], az[8], nwx[8], rowm[8];
    {
        const int r0 = rbase + rg * 8;                  // 16B-aligned start
        const float4* Ar = (const float4*)(A + (size_t)r0 * 3);
        float av[24];
        #pragma unroll
        for (int i = 0; i < 6; i++) *(float4*)&av[4 * i] = Ar[i];
        #pragma unroll
        for (int r = 0; r < 8; r++) {
            ax[r] = av[3 * r + 0];
            ay[r] = av[3 * r + 1];
            az[r] = av[3 * r + 2];
            nwx[r] = -0.5f * fmaf(ax[r], ax[r], fmaf(ay[r], ay[r], az[r] * az[r]));
            rowm[r] = -3.0e38f;
        }
    }

    // Preload chunk 0's column for this thread.
    float nbx, nby, nbz;
    {
        const float* p = Bp + (size_t)(cb + tid) * 3;
        nbx = p[0]; nby = p[1]; nbz = p[2];
    }

    for (int ch = 0; ch < NCH; ch++) {
        __syncthreads();                                // sB free, prev sM reads done
        {
            const float bx = nbx, by = nby, bz = nbz;
            const float nwy = -0.5f * fmaf(bx, bx, fmaf(by, by, bz * bz));
            sB[tid] = make_float4(bx, by, bz, nwy);
        }
        __syncthreads();

        // Prefetch next chunk's column (hidden under compute).
        if (ch + 1 < NCH) {
            const float* p = Bp + (size_t)(cb + (ch + 1) * CHUNK + tid) * 3;
            nbx = p[0]; nby = p[1]; nbz = p[2];
        }

        float colm[16];
        #pragma unroll
        for (int k = 0; k < 16; k++) colm[k] = -3.0e38f;

        // Main compute: 16 cols x 8 rows, scalar FFMA, maxes in regs.
        #pragma unroll
        for (int cc = 0; cc < 16; cc++) {
            const float4 v = sB[cc * 16 + cg];          // lanes -> consecutive float4s
            float cm = colm[cc];
            #pragma unroll
            for (int r = 0; r < 8; r++) {
                float t = fmaf(az[r], v.z, v.w);        // az*bz - y^2/2
                t = fmaf(ay[r], v.y, t);                // + ay*by
                t = fmaf(ax[r], v.x, t);                // + ax*bx = x.y - y^2/2
                rowm[r] = fmaxf(rowm[r], t);            // row side (-x^2/2 folded later)
                cm = fmaxf(cm, t + nwx[r]);             // col side: -d^2/2
            }
            colm[cc] = cm;
        }

        // Col merge for this chunk: 16 rg writers per col through sM.
        #pragma unroll
        for (int cc = 0; cc < 16; cc++)
            sM[rg * MST + cc * 16 + cg] = colm[cc];
        __syncthreads();
        {
            float m = sM[tid];                          // col = tid of this chunk
            #pragma unroll
            for (int g = 1; g < 16; g++) m = fmaxf(m, sM[g * MST + tid]);
            atomicMax(&g_cmax[(size_t)b * NPTS + cb + ch * CHUNK + tid], enc(m));
        }
    }

    // ---- Row merge: fold -x^2/2, transpose through smem, one RED per row ----
    __syncthreads();
    #pragma unroll
    for (int r = 0; r < 8; r++)
        sM[cg * MST + rg * 8 + r] = rowm[r] + nwx[r];
    __syncthreads();
    if (tid < RT) {
        float m = sM[tid];
        #pragma unroll
        for (int g = 1; g < 16; g++) m = fmaxf(m, sM[g * MST + tid]);
        atomicMax(&g_rmax[(size_t)b * NPTS + rbase + tid], enc(m));
    }
}

// 4 points per thread: decode max u = -d^2/2, sqrt, reduce, reset.
__global__ __launch_bounds__(FIN_THREADS)
void chamfer_finalize(float* __restrict__ out) {
    const int t4 = (blockIdx.x * FIN_THREADS + threadIdx.x) * 4;
    const int dir = t4 >> 15;
    const int rem = t4 & 32767;
    unsigned* __restrict__ g = (dir == 0) ? g_rmax : g_cmax;

    uint4 v = *(uint4*)&g[rem];
    *(uint4*)&g[rem] = make_uint4(0u, 0u, 0u, 0u);   // reset for next replay
    float s = sqrtf(fmaxf(-2.0f * dec(v.x), 0.0f))
            + sqrtf(fmaxf(-2.0f * dec(v.y), 0.0f))
            + sqrtf(fmaxf(-2.0f * dec(v.z), 0.0f))
            + sqrtf(fmaxf(-2.0f * dec(v.w), 0.0f));

    #pragma unroll
    for (int off = 16; off > 0; off >>= 1)
        s += __shfl_down_sync(0xFFFFFFFFu, s, off);

    __shared__ float warp_sums[FIN_THREADS / 32];
    __shared__ bool is_last;
    const int tid = threadIdx.x;
    if ((tid & 31) == 0) warp_sums[tid >> 5] = s;
    __syncthreads();
    if (tid == 0) {
        float bs = 0.0f;
        #pragma unroll
        for (int w = 0; w < FIN_THREADS / 32; w++) bs += warp_sums[w];
        g_bsum[blockIdx.x] = bs;
        __threadfence();
        const unsigned done = atomicAdd(&g_counter, 1u) + 1u;
        is_last = (done == FIN_BLOCKS);
    }
    __syncthreads();

    if (is_last && tid < 32) {
        float v2 = g_bsum[tid];
        #pragma unroll
        for (int k = 1; k < FIN_BLOCKS / 32; k++)
            v2 += g_bsum[k * 32 + tid];
        #pragma unroll
        for (int off = 16; off > 0; off >>= 1)
            v2 += __shfl_down_sync(0xFFFFFFFFu, v2, off);
        if (tid == 0) {
            out[0] = v2 * (1.0f / (float)(BATCH * NPTS));
            g_counter = 0u;
        }
    }
}

extern "C" void kernel_launch(void* const* d_in, const int* in_sizes, int n_in,
                              void* d_out, int out_size) {
    const float* pred  = (const float*)d_in[0];
    const float* label = (const float*)d_in[1];
    float* out = (float*)d_out;

    dim3 grid(NPTS / RT, CSPLIT, BATCH);   // 64 x 4 x 4 = 1024 blocks
    chamfer_main<<<grid, THREADS>>>(pred, label);
    chamfer_finalize<<<FIN_BLOCKS, FIN_THREADS>>>(out);
}

// round 14
// speedup vs baseline: 1.2077x; 1.0290x over previous
#include <cuda_runtime.h>
#include <math.h>

#define BATCH 4
#define NPTS  8192
#define RT 128                      // rows per tile
#define CPT 1024                    // cols per tile
#define CHUNK 256                   // cols staged per chunk
#define NCH (CPT / CHUNK)           // 4 chunks per tile
#define THREADS 256
#define NSM 148
#define OCC 3
#define PBLOCKS (NSM * OCC)         // 444 persistent blocks
#define RCH (NPTS / RT)             // 64 row chunks
#define CCH (NPTS / CPT)            // 8 col chunks
#define NTILES (RCH * BATCH * CCH)  // 2048 tiles
#define FIN_THREADS 256
#define FIN_BLOCKS 64
#define MST 257                     // padded smem row stride (floats)

__device__ unsigned g_rmax[BATCH * NPTS];   // pred  -> label
__device__ unsigned g_cmax[BATCH * NPTS];   // label -> pred
__device__ float    g_bsum[FIN_BLOCKS];
__device__ unsigned g_tile = 0;             // dynamic tile counter
__device__ unsigned g_counter = 0;

__device__ __forceinline__ unsigned enc(float f) {
    unsigned u = __float_as_uint(f);
    return u ^ ((unsigned)((int)u >> 31) | 0x80000000u);
}
__device__ __forceinline__ float dec(unsigned k) {
    unsigned u = (k & 0x80000000u) ? (k ^ 0x80000000u) : ~k;
    return __uint_as_float(u);
}

// Persistent blocks steal 128x1024 tiles. Per entry u = x.y - x^2/2 - y^2/2
// = -d^2/2 feeds BOTH direction maxes. Tile id = rc*32 + b*8 + cc (cc fastest)
// so consecutive stolen tiles usually share the same A rows.
__global__ __launch_bounds__(THREADS, OCC)
void chamfer_main(const float* __restrict__ pred,
                  const float* __restrict__ label) {
    __shared__ float4 sB[CHUNK];        // (bx, by, bz, nwy) per col, 4 KB
    __shared__ float  sM[16 * MST];     // merge transpose buffer, ~16 KB
    __shared__ unsigned s_t;

    const int tid = threadIdx.x;
    const int rg  = tid >> 4;
    const int cg  = tid & 15;

    float ax[8], ay[8], az[8], nwx[8], rowm[8];
    int prev_key = -1;

    for (;;) {
        __syncthreads();                            // protect s_t + prior sM reads
        if (tid == 0) s_t = atomicAdd(&g_tile, 1u);
        __syncthreads();
        const unsigned t = s_t;
        if (t >= (unsigned)NTILES) break;

        const int rc = t >> 5;                      // t / (BATCH*CCH)
        const int rem = t & 31;
        const int b  = rem >> 3;
        const int cc0 = rem & 7;
        const int rbase = rc * RT;
        const int cb    = cc0 * CPT;
        const float* __restrict__ A  = pred  + (size_t)b * NPTS * 3;
        const float* __restrict__ Bp = label + (size_t)b * NPTS * 3;

        // ---- A-row prologue (skipped when rows unchanged) ----
        const int key = (b << 16) | rc;
        if (key != prev_key) {
            prev_key = key;
            const int r0 = rbase + rg * 8;          // 16B-aligned start
            const float4* Ar = (const float4*)(A + (size_t)r0 * 3);
            float av[24];
            #pragma unroll
            for (int i = 0; i < 6; i++) *(float4*)&av[4 * i] = Ar[i];
            #pragma unroll
            for (int r = 0; r < 8; r++) {
                ax[r] = av[3 * r + 0];
                ay[r] = av[3 * r + 1];
                az[r] = av[3 * r + 2];
                nwx[r] = -0.5f * fmaf(ax[r], ax[r],
                                      fmaf(ay[r], ay[r], az[r] * az[r]));
            }
        }
        #pragma unroll
        for (int r = 0; r < 8; r++) rowm[r] = -3.0e38f;

        // Preload chunk 0's column for this thread.
        float nbx, nby, nbz;
        {
            const float* p = Bp + (size_t)(cb + tid) * 3;
            nbx = p[0]; nby = p[1]; nbz = p[2];
        }

        for (int ch = 0; ch < NCH; ch++) {
            __syncthreads();                        // sB free, prev sM reads done
            {
                const float bx = nbx, by = nby, bz = nbz;
                const float nwy = -0.5f * fmaf(bx, bx, fmaf(by, by, bz * bz));
                sB[tid] = make_float4(bx, by, bz, nwy);
            }
            __syncthreads();

            if (ch + 1 < NCH) {                     // prefetch next chunk's col
                const float* p = Bp + (size_t)(cb + (ch + 1) * CHUNK + tid) * 3;
                nbx = p[0]; nby = p[1]; nbz = p[2];
            }

            float colm[16];
            #pragma unroll
            for (int k = 0; k < 16; k++) colm[k] = -3.0e38f;

            // 16 cols x 8 rows, scalar FFMA, both maxes on the same u.
            #pragma unroll
            for (int cc = 0; cc < 16; cc++) {
                const float4 v = sB[cc * 16 + cg];  // consecutive float4s
                float cm = colm[cc];
                #pragma unroll
                for (int r = 0; r < 8; r++) {
                    float u = fmaf(az[r], v.z, v.w);    // az*bz - y^2/2
                    u = fmaf(ay[r], v.y, u);            // + ay*by
                    u = fmaf(ax[r], v.x, u);            // + ax*bx
                    u += nwx[r];                        // - x^2/2 => -d^2/2
                    rowm[r] = fmaxf(rowm[r], u);
                    cm = fmaxf(cm, u);
                }
                colm[cc] = cm;
            }

            // Col merge for this chunk through sM (16 rg writers per col).
            #pragma unroll
            for (int cc = 0; cc < 16; cc++)
                sM[rg * MST + cc * 16 + cg] = colm[cc];
            __syncthreads();
            {
                float m = sM[tid];
                #pragma unroll
                for (int g = 1; g < 16; g++) m = fmaxf(m, sM[g * MST + tid]);
                atomicMax(&g_cmax[(size_t)b * NPTS + cb + ch * CHUNK + tid],
                          enc(m));
            }
        }

        // ---- Row merge: transpose through smem, one RED per row ----
        __syncthreads();
        #pragma unroll
        for (int r = 0; r < 8; r++)
            sM[cg * MST + rg * 8 + r] = rowm[r];
        __syncthreads();
        if (tid < RT) {
            float m = sM[tid];
            #pragma unroll
            for (int g = 1; g < 16; g++) m = fmaxf(m, sM[g * MST + tid]);
            atomicMax(&g_rmax[(size_t)b * NPTS + rbase + tid], enc(m));
        }
    }
}

// 4 points per thread: decode max u = -d^2/2, sqrt, reduce, reset counters.
__global__ __launch_bounds__(FIN_THREADS)
void chamfer_finalize(float* __restrict__ out) {
    const int t4 = (blockIdx.x * FIN_THREADS + threadIdx.x) * 4;
    const int dir = t4 >> 15;
    const int rem = t4 & 32767;
    unsigned* __restrict__ g = (dir == 0) ? g_rmax : g_cmax;

    uint4 v = *(uint4*)&g[rem];
    *(uint4*)&g[rem] = make_uint4(0u, 0u, 0u, 0u);   // reset for next replay
    float s = sqrtf(fmaxf(-2.0f * dec(v.x), 0.0f))
            + sqrtf(fmaxf(-2.0f * dec(v.y), 0.0f))
            + sqrtf(fmaxf(-2.0f * dec(v.z), 0.0f))
            + sqrtf(fmaxf(-2.0f * dec(v.w), 0.0f));

    #pragma unroll
    for (int off = 16; off > 0; off >>= 1)
        s += __shfl_down_sync(0xFFFFFFFFu, s, off);

    __shared__ float warp_sums[FIN_THREADS / 32];
    __shared__ bool is_last;
    const int tid = threadIdx.x;
    if ((tid & 31) == 0) warp_sums[tid >> 5] = s;
    __syncthreads();
    if (tid == 0) {
        float bs = 0.0f;
        #pragma unroll
        for (int w = 0; w < FIN_THREADS / 32; w++) bs += warp_sums[w];
        g_bsum[blockIdx.x] = bs;
        __threadfence();
        const unsigned done = atomicAdd(&g_counter, 1u) + 1u;
        is_last = (done == FIN_BLOCKS);
    }
    __syncthreads();

    if (is_last && tid < 32) {
        float v2 = g_bsum[tid];
        #pragma unroll
        for (int k = 1; k < FIN_BLOCKS / 32; k++)
            v2 += g_bsum[k * 32 + tid];
        #pragma unroll
        for (int off = 16; off > 0; off >>= 1)
            v2 += __shfl_down_sync(0xFFFFFFFFu, v2, off);
        if (tid == 0) {
            out[0] = v2 * (1.0f / (float)(BATCH * NPTS));
            g_counter = 0u;
            g_tile = 0u;               // reset tile counter for next replay
        }
    }
}

extern "C" void kernel_launch(void* const* d_in, const int* in_sizes, int n_in,
                              void* d_out, int out_size) {
    const float* pred  = (const float*)d_in[0];
    const float* label = (const float*)d_in[1];
    float* out = (float*)d_out;

    chamfer_main<<<PBLOCKS, THREADS>>>(pred, label);
    chamfer_finalize<<<FIN_BLOCKS, FIN_THREADS>>>(out);
}

// round 15
// speedup vs baseline: 1.2858x; 1.0647x over previous
#include <cuda_runtime.h>
#include <math.h>

#define BATCH 4
#define NPTS  8192
#define RT 128                      // rows per block
#define CSPLIT 4
#define CPB (NPTS / CSPLIT)         // 2048 cols per block
#define CHUNK 256                   // cols staged per chunk
#define NCH (CPB / CHUNK)           // 8 chunks
#define THREADS 256
// rg = tid>>4 (16 row groups x 8 rows), cg = tid&15 (16 col slots x 16 cols/chunk)
#define FIN_THREADS 256
#define FIN_BLOCKS 256              // 1 point per thread
#define MST 257                     // padded smem row stride (floats)

__device__ unsigned g_rmax[BATCH * NPTS];   // pred  -> label
__device__ unsigned g_cmax[BATCH * NPTS];   // label -> pred

__device__ __forceinline__ unsigned enc(float f) {
    unsigned u = __float_as_uint(f);
    return u ^ ((unsigned)((int)u >> 31) | 0x80000000u);
}
__device__ __forceinline__ float dec(unsigned k) {
    unsigned u = (k & 0x80000000u) ? (k ^ 0x80000000u) : ~k;
    return __uint_as_float(u);
}

// One block: 128 pred rows x 2048 label cols (8 prefetched 256-col chunks).
// Per entry u = x.y - x^2/2 - y^2/2 = -d^2/2; BOTH direction maxes use u.
// Block 0 also zeroes out[0] so finalize can accumulate with atomicAdd.
__global__ __launch_bounds__(THREADS, 3)
void chamfer_main(const float* __restrict__ pred,
                  const float* __restrict__ label,
                  float* __restrict__ out) {
    const int b      = blockIdx.z;
    const int rbase  = blockIdx.x * RT;
    const int cb     = blockIdx.y * CPB;
    const float* __restrict__ A  = pred  + (size_t)b * NPTS * 3;
    const float* __restrict__ Bp = label + (size_t)b * NPTS * 3;

    if (blockIdx.x == 0 && blockIdx.y == 0 && blockIdx.z == 0 && threadIdx.x == 0)
        out[0] = 0.0f;              // visible to finalize via stream order

    __shared__ float4 sB[CHUNK];        // (bx, by, bz, nwy) per col, 4 KB
    __shared__ float  sM[16 * MST];     // merge transpose buffer, ~16 KB

    const int tid = threadIdx.x;
    const int rg  = tid >> 4;
    const int cg  = tid & 15;

    // ---- Prologue: this thread's 8 A rows (96 contiguous bytes) ----
    float ax[8], ay[8], az[8], nwx[8], rowm[8];
    {
        const int r0 = rbase + rg * 8;                  // 16B-aligned start
        const float4* Ar = (const float4*)(A + (size_t)r0 * 3);
        float av[24];
        #pragma unroll
        for (int i = 0; i < 6; i++) *(float4*)&av[4 * i] = Ar[i];
        #pragma unroll
        for (int r = 0; r < 8; r++) {
            ax[r] = av[3 * r + 0];
            ay[r] = av[3 * r + 1];
            az[r] = av[3 * r + 2];
            nwx[r] = -0.5f * fmaf(ax[r], ax[r], fmaf(ay[r], ay[r], az[r] * az[r]));
            rowm[r] = -3.0e38f;
        }
    }

    // Preload chunk 0's column for this thread.
    float nbx, nby, nbz;
    {
        const float* p = Bp + (size_t)(cb + tid) * 3;
        nbx = p[0]; nby = p[1]; nbz = p[2];
    }

    for (int ch = 0; ch < NCH; ch++) {
        __syncthreads();                                // sB free, prev sM reads done
        {
            const float bx = nbx, by = nby, bz = nbz;
            const float nwy = -0.5f * fmaf(bx, bx, fmaf(by, by, bz * bz));
            sB[tid] = make_float4(bx, by, bz, nwy);
        }
        __syncthreads();

        // Prefetch next chunk's column (hidden under compute).
        if (ch + 1 < NCH) {
            const float* p = Bp + (size_t)(cb + (ch + 1) * CHUNK + tid) * 3;
            nbx = p[0]; nby = p[1]; nbz = p[2];
        }

        float colm[16];
        #pragma unroll
        for (int k = 0; k < 16; k++) colm[k] = -3.0e38f;

        // Main compute: 16 cols x 8 rows, scalar FFMA, maxes in regs.
        #pragma unroll
        for (int cc = 0; cc < 16; cc++) {
            const float4 v = sB[cc * 16 + cg];          // lanes -> consecutive float4s
            float cm = colm[cc];
            #pragma unroll
            for (int r = 0; r < 8; r++) {
                float t = fmaf(az[r], v.z, v.w);        // az*bz - y^2/2
                t = fmaf(ay[r], v.y, t);                // + ay*by
                t = fmaf(ax[r], v.x, t);                // + ax*bx
                t += nwx[r];                            // - x^2/2  => -d^2/2
                rowm[r] = fmaxf(rowm[r], t);
                cm = fmaxf(cm, t);
            }
            colm[cc] = cm;
        }

        // Col merge for this chunk: 16 rg writers per col through sM.
        #pragma unroll
        for (int cc = 0; cc < 16; cc++)
            sM[rg * MST + cc * 16 + cg] = colm[cc];
        __syncthreads();
        {
            float m = sM[tid];                          // col = tid of this chunk
            #pragma unroll
            for (int g = 1; g < 16; g++) m = fmaxf(m, sM[g * MST + tid]);
            atomicMax(&g_cmax[(size_t)b * NPTS + cb + ch * CHUNK + tid], enc(m));
        }
    }

    // ---- Row merge: transpose through smem, one RED per row ----
    __syncthreads();
    #pragma unroll
    for (int r = 0; r < 8; r++)
        sM[cg * MST + rg * 8 + r] = rowm[r];
    __syncthreads();
    if (tid < RT) {
        float m = sM[tid];
        #pragma unroll
        for (int g = 1; g < 16; g++) m = fmaxf(m, sM[g * MST + tid]);
        atomicMax(&g_rmax[(size_t)b * NPTS + rbase + tid], enc(m));
    }
}

// One point per thread: decode max u = -d^2/2, sqrt, block-reduce,
// one float atomicAdd per block. Resets slots for the next graph replay.
__global__ __launch_bounds__(FIN_THREADS)
void chamfer_finalize(float* __restrict__ out) {
    const int idx = blockIdx.x * FIN_THREADS + threadIdx.x;   // 0 .. 65535
    const int dir = idx >> 15;
    const int rem = idx & 32767;
    unsigned* __restrict__ g = (dir == 0) ? g_rmax : g_cmax;

    const unsigned k = g[rem];
    g[rem] = 0u;                                   // reset for next replay
    float s = sqrtf(fmaxf(-2.0f * dec(k), 0.0f));

    #pragma unroll
    for (int off = 16; off > 0; off >>= 1)
        s += __shfl_down_sync(0xFFFFFFFFu, s, off);

    __shared__ float warp_sums[FIN_THREADS / 32];
    const int tid = threadIdx.x;
    if ((tid & 31) == 0) warp_sums[tid >> 5] = s;
    __syncthreads();
    if (tid == 0) {
        float bs = 0.0f;
        #pragma unroll
        for (int w = 0; w < FIN_THREADS / 32; w++) bs += warp_sums[w];
        atomicAdd(out, bs * (1.0f / (float)(BATCH * NPTS)));
    }
}

extern "C" void kernel_launch(void* const* d_in, const int* in_sizes, int n_in,
                              void* d_out, int out_size) {
    const float* pred  = (const float*)d_in[0];
    const float* label = (const float*)d_in[1];
    float* out = (float*)d_out;

    dim3 grid(NPTS / RT, CSPLIT, BATCH);   // 64 x 4 x 4 = 1024 blocks
    chamfer_main<<<grid, THREADS>>>(pred, label, out);
    chamfer_finalize<<<FIN_BLOCKS, FIN_THREADS>>>(out);
}